// round 1
// baseline (speedup 1.0000x reference)
#include <cuda_runtime.h>
#include <cuda_bf16.h>

#define Bn 64
#define Sn 1024
#define Vn 32000
#define Dn 1024
#define Hn 1024
#define En 1024
#define An 1024

// ---------------- scratch (no allocs allowed) ----------------
__device__ float g_q[Bn * An];          // q = h0[-1] @ Wa_h^T + ba_h
__device__ float g_score[Bn * Sn];      // pre-softmax scores
__device__ float g_x[Bn * (Dn + En)];   // [embedded, context]
__device__ float g_gates[Bn * 4 * Hn];  // LSTM gate pre-activations

// ---------------- embedding gather (writes first half of x) ----------------
__global__ void embed_kernel(const int* __restrict__ input_step,
                             const float* __restrict__ emb,
                             float* __restrict__ xbuf) {
    int b = blockIdx.x;
    int row = input_step[b];
    const float* src = emb + (size_t)row * Dn;
    float* dst = xbuf + (size_t)b * (Dn + En);
    for (int d = threadIdx.x; d < Dn; d += blockDim.x) dst[d] = src[d];
}

// ---------------- generic small-M GEMM: C[64,N] = A[64,K] @ W[N,K]^T (+bias[+bias2]) ----------------
// grid.x = N/64, block = 256 threads, 4x4 micro-tile per thread, BK=16
__global__ void gemm_nt(const float* __restrict__ Amat,  // 64 x K row-major
                        const float* __restrict__ Wmat,  // N x K row-major
                        const float* __restrict__ bias,  // or null
                        const float* __restrict__ bias2, // or null
                        float* __restrict__ Cmat,        // 64 x N row-major
                        int K, int N, int accumulate) {
    __shared__ float As[16][64];
    __shared__ float Ws[16][64];

    int tid = threadIdx.x;
    int tr = tid >> 4;        // 0..15
    int tc = tid & 15;        // 0..15
    int n0 = blockIdx.x * 64;

    int lm = tid >> 2;        // 0..63 (row within tile)
    int lk = (tid & 3) * 4;   // 0,4,8,12

    float acc[4][4];
#pragma unroll
    for (int i = 0; i < 4; i++)
#pragma unroll
        for (int j = 0; j < 4; j++) acc[i][j] = 0.f;

    for (int k0 = 0; k0 < K; k0 += 16) {
        float4 a = *(const float4*)&Amat[(size_t)lm * K + k0 + lk];
        float4 w = *(const float4*)&Wmat[(size_t)(n0 + lm) * K + k0 + lk];
        As[lk + 0][lm] = a.x; As[lk + 1][lm] = a.y; As[lk + 2][lm] = a.z; As[lk + 3][lm] = a.w;
        Ws[lk + 0][lm] = w.x; Ws[lk + 1][lm] = w.y; Ws[lk + 2][lm] = w.z; Ws[lk + 3][lm] = w.w;
        __syncthreads();
#pragma unroll
        for (int k = 0; k < 16; k++) {
            float4 av = *(const float4*)&As[k][tr * 4];
            float4 wv = *(const float4*)&Ws[k][tc * 4];
            float ar[4] = {av.x, av.y, av.z, av.w};
            float wr[4] = {wv.x, wv.y, wv.z, wv.w};
#pragma unroll
            for (int i = 0; i < 4; i++)
#pragma unroll
                for (int j = 0; j < 4; j++) acc[i][j] += ar[i] * wr[j];
        }
        __syncthreads();
    }

#pragma unroll
    for (int i = 0; i < 4; i++) {
        int m = tr * 4 + i;
#pragma unroll
        for (int j = 0; j < 4; j++) {
            int n = n0 + tc * 4 + j;
            float v = acc[i][j];
            if (bias)  v += bias[n];
            if (bias2) v += bias2[n];
            if (accumulate) v += Cmat[(size_t)m * N + n];
            Cmat[(size_t)m * N + n] = v;
        }
    }
}

// ---------------- score init: score[i] = bva ----------------
__global__ void score_init_kernel(const float* __restrict__ bva, float* __restrict__ score) {
    int i = blockIdx.x * blockDim.x + threadIdx.x;
    if (i < Bn * Sn) score[i] = bva[0];
}

// ---------------- fused attention score GEMM ----------------
// score[m] += sum_n va[n] * tanh( enc[m,:]·Wa_e[n,:] + q[b,n] + ba_e[n] )
// m = b*S + s ; grid = (BS/64, A/64) ; block 256
__global__ void score_gemm(const float* __restrict__ enc,
                           const float* __restrict__ Wa_e,
                           const float* __restrict__ ba_e,
                           const float* __restrict__ q,
                           const float* __restrict__ va,
                           float* __restrict__ score) {
    __shared__ float As[16][64];
    __shared__ float Ws[16][64];
    __shared__ float red[64][17];

    int tid = threadIdx.x;
    int tr = tid >> 4;
    int tc = tid & 15;
    int m0 = blockIdx.x * 64;
    int n0 = blockIdx.y * 64;
    int b = m0 >> 10;  // / S

    int lm = tid >> 2;
    int lk = (tid & 3) * 4;

    float acc[4][4];
#pragma unroll
    for (int i = 0; i < 4; i++)
#pragma unroll
        for (int j = 0; j < 4; j++) acc[i][j] = 0.f;

    const int K = En;
    for (int k0 = 0; k0 < K; k0 += 16) {
        float4 a = *(const float4*)&enc[(size_t)(m0 + lm) * K + k0 + lk];
        float4 w = *(const float4*)&Wa_e[(size_t)(n0 + lm) * K + k0 + lk];
        As[lk + 0][lm] = a.x; As[lk + 1][lm] = a.y; As[lk + 2][lm] = a.z; As[lk + 3][lm] = a.w;
        Ws[lk + 0][lm] = w.x; Ws[lk + 1][lm] = w.y; Ws[lk + 2][lm] = w.z; Ws[lk + 3][lm] = w.w;
        __syncthreads();
#pragma unroll
        for (int k = 0; k < 16; k++) {
            float4 av = *(const float4*)&As[k][tr * 4];
            float4 wv = *(const float4*)&Ws[k][tc * 4];
            float ar[4] = {av.x, av.y, av.z, av.w};
            float wr[4] = {wv.x, wv.y, wv.z, wv.w};
#pragma unroll
            for (int i = 0; i < 4; i++)
#pragma unroll
                for (int j = 0; j < 4; j++) acc[i][j] += ar[i] * wr[j];
        }
        __syncthreads();
    }

    // epilogue: tanh + weighted row-sum
    float rsum[4] = {0.f, 0.f, 0.f, 0.f};
#pragma unroll
    for (int j = 0; j < 4; j++) {
        int n = n0 + tc * 4 + j;
        float qb = q[b * An + n] + ba_e[n];
        float vn = va[n];
#pragma unroll
        for (int i = 0; i < 4; i++) {
            rsum[i] += vn * tanhf(acc[i][j] + qb);
        }
    }
#pragma unroll
    for (int i = 0; i < 4; i++) red[tr * 4 + i][tc] = rsum[i];
    __syncthreads();
    if (tid < 64) {
        float s = 0.f;
#pragma unroll
        for (int t = 0; t < 16; t++) s += red[tid][t];
        atomicAdd(&score[m0 + tid], s);
    }
}

// ---------------- softmax over S per batch row ----------------
__global__ void softmax_kernel(const float* __restrict__ score, float* __restrict__ attn) {
    __shared__ float sh[Sn];
    __shared__ float red[256];
    int b = blockIdx.x;
    int tid = threadIdx.x;

    float lmax = -3.4e38f;
    for (int s = tid; s < Sn; s += 256) {
        float v = score[b * Sn + s];
        sh[s] = v;
        lmax = fmaxf(lmax, v);
    }
    red[tid] = lmax;
    __syncthreads();
    for (int off = 128; off > 0; off >>= 1) {
        if (tid < off) red[tid] = fmaxf(red[tid], red[tid + off]);
        __syncthreads();
    }
    float m = red[0];
    __syncthreads();

    float lsum = 0.f;
    for (int s = tid; s < Sn; s += 256) {
        float e = expf(sh[s] - m);
        sh[s] = e;
        lsum += e;
    }
    red[tid] = lsum;
    __syncthreads();
    for (int off = 128; off > 0; off >>= 1) {
        if (tid < off) red[tid] += red[tid + off];
        __syncthreads();
    }
    float inv = 1.f / red[0];
    __syncthreads();

    for (int s = tid; s < Sn; s += 256) attn[b * Sn + s] = sh[s] * inv;
}

// ---------------- context = attn @ enc (writes second half of x) ----------------
// grid (B, E/256)
__global__ void context_kernel(const float* __restrict__ enc,
                               const float* __restrict__ attn,
                               float* __restrict__ xbuf) {
    __shared__ float w[Sn];
    int b = blockIdx.x;
    int e = blockIdx.y * 256 + threadIdx.x;
    for (int s = threadIdx.x; s < Sn; s += 256) w[s] = attn[b * Sn + s];
    __syncthreads();
    const float* ep = enc + (size_t)b * Sn * En + e;
    float acc = 0.f;
#pragma unroll 8
    for (int s = 0; s < Sn; s++) acc += w[s] * ep[(size_t)s * En];
    xbuf[(size_t)b * (Dn + En) + Dn + e] = acc;
}

// ---------------- LSTM pointwise ----------------
__global__ void lstm_pointwise(const float* __restrict__ gates,
                               const float* __restrict__ cprev,
                               float* __restrict__ hout,
                               float* __restrict__ cout) {
    int idx = blockIdx.x * 256 + threadIdx.x;
    if (idx >= Bn * Hn) return;
    int b = idx >> 10;
    int h = idx & 1023;
    const float* g = gates + (size_t)b * 4 * Hn;
    float ig = 1.f / (1.f + expf(-g[h]));
    float fg = 1.f / (1.f + expf(-g[Hn + h]));
    float gg = tanhf(g[2 * Hn + h]);
    float og = 1.f / (1.f + expf(-g[3 * Hn + h]));
    float c = fg * cprev[idx] + ig * gg;
    hout[idx] = og * tanhf(c);
    cout[idx] = c;
}

// ---------------- launcher ----------------
extern "C" void kernel_launch(void* const* d_in, const int* in_sizes, int n_in,
                              void* d_out, int out_size) {
    const int*   input_step = (const int*)d_in[0];
    const float* h0    = (const float*)d_in[1];
    const float* c0    = (const float*)d_in[2];
    const float* enc   = (const float*)d_in[3];
    const float* emb   = (const float*)d_in[4];
    const float* Wa_h  = (const float*)d_in[5];
    const float* ba_h  = (const float*)d_in[6];
    const float* Wa_e  = (const float*)d_in[7];
    const float* ba_e  = (const float*)d_in[8];
    const float* va    = (const float*)d_in[9];
    const float* bva   = (const float*)d_in[10];
    const float* Wih0  = (const float*)d_in[11];
    const float* Whh0  = (const float*)d_in[12];
    const float* bih0  = (const float*)d_in[13];
    const float* bhh0  = (const float*)d_in[14];
    const float* Wih1  = (const float*)d_in[15];
    const float* Whh1  = (const float*)d_in[16];
    const float* bih1  = (const float*)d_in[17];
    const float* bhh1  = (const float*)d_in[18];
    const float* Wout  = (const float*)d_in[19];
    const float* bout  = (const float*)d_in[20];

    float* out = (float*)d_out;
    float* out_logits = out;                      // B*V
    float* out_h      = out_logits + Bn * Vn;     // 2*B*H
    float* out_c      = out_h + 2 * Bn * Hn;      // 2*B*H
    float* out_attn   = out_c + 2 * Bn * Hn;      // B*S

    float* q_buf;     cudaGetSymbolAddress((void**)&q_buf, g_q);
    float* score_buf; cudaGetSymbolAddress((void**)&score_buf, g_score);
    float* x_buf;     cudaGetSymbolAddress((void**)&x_buf, g_x);
    float* gates_buf; cudaGetSymbolAddress((void**)&gates_buf, g_gates);

    // 1. embedding gather -> x[:, :D]
    embed_kernel<<<Bn, 256>>>(input_step, emb, x_buf);

    // 2. q = h0[1] @ Wa_h^T + ba_h
    gemm_nt<<<An / 64, 256>>>(h0 + Bn * Hn, Wa_h, ba_h, nullptr, q_buf, Hn, An, 0);

    // 3. score init to bva, then fused score GEMM
    score_init_kernel<<<(Bn * Sn + 255) / 256, 256>>>(bva, score_buf);
    {
        dim3 grid(Bn * Sn / 64, An / 64);
        score_gemm<<<grid, 256>>>(enc, Wa_e, ba_e, q_buf, va, score_buf);
    }

    // 4. softmax -> attn_w output
    softmax_kernel<<<Bn, 256>>>(score_buf, out_attn);

    // 5. context -> x[:, D:]
    {
        dim3 grid(Bn, En / 256);
        context_kernel<<<grid, 256>>>(enc, out_attn, x_buf);
    }

    // 6. LSTM layer 0: gates = x @ Wih0^T + h0[0] @ Whh0^T + bih0 + bhh0
    gemm_nt<<<4 * Hn / 64, 256>>>(x_buf, Wih0, bih0, bhh0, gates_buf, Dn + En, 4 * Hn, 0);
    gemm_nt<<<4 * Hn / 64, 256>>>(h0, Whh0, nullptr, nullptr, gates_buf, Hn, 4 * Hn, 1);
    lstm_pointwise<<<(Bn * Hn + 255) / 256, 256>>>(gates_buf, c0, out_h, out_c);

    // 7. LSTM layer 1: gates = h1 @ Wih1^T + h0[1] @ Whh1^T + bih1 + bhh1
    gemm_nt<<<4 * Hn / 64, 256>>>(out_h, Wih1, bih1, bhh1, gates_buf, Hn, 4 * Hn, 0);
    gemm_nt<<<4 * Hn / 64, 256>>>(h0 + Bn * Hn, Whh1, nullptr, nullptr, gates_buf, Hn, 4 * Hn, 1);
    lstm_pointwise<<<(Bn * Hn + 255) / 256, 256>>>(gates_buf, c0 + Bn * Hn,
                                                   out_h + Bn * Hn, out_c + Bn * Hn);

    // 8. logits = h2 @ Wout^T + bout
    gemm_nt<<<Vn / 64, 256>>>(out_h + Bn * Hn, Wout, bout, nullptr, out_logits, Hn, Vn, 0);
}

// round 2
// speedup vs baseline: 2.8938x; 2.8938x over previous
#include <cuda_runtime.h>
#include <cuda_bf16.h>

#define Bn 64
#define Sn 1024
#define Vn 32000
#define Dn 1024
#define Hn 1024
#define En 1024
#define An 1024

// ---------------- scratch (no allocs allowed) ----------------
__device__ float g_q[Bn * An];          // q = h0[-1] @ Wa_h^T + ba_h
__device__ float g_score[Bn * Sn];      // pre-softmax scores
__device__ float g_x[Bn * (Dn + En)];   // [embedded, context]
__device__ float g_gates[Bn * 4 * Hn];  // LSTM gate pre-activations

// ---------------- helpers ----------------
__device__ __forceinline__ unsigned f2tf(float f) {
    unsigned u;
    asm("cvt.rna.tf32.f32 %0, %1;" : "=r"(u) : "f"(f));
    return u;
}

__device__ __forceinline__ void mma_tf32(float* c, const unsigned* a, const unsigned* b) {
    asm volatile(
        "mma.sync.aligned.m16n8k8.row.col.f32.tf32.tf32.f32 "
        "{%0,%1,%2,%3}, {%4,%5,%6,%7}, {%8,%9}, {%0,%1,%2,%3};"
        : "+f"(c[0]), "+f"(c[1]), "+f"(c[2]), "+f"(c[3])
        : "r"(a[0]), "r"(a[1]), "r"(a[2]), "r"(a[3]), "r"(b[0]), "r"(b[1]));
}

// ---------------- embedding gather (writes first half of x) ----------------
__global__ void embed_kernel(const int* __restrict__ input_step,
                             const float* __restrict__ emb,
                             float* __restrict__ xbuf) {
    int b = blockIdx.x;
    int row = input_step[b];
    const float* src = emb + (size_t)row * Dn;
    float* dst = xbuf + (size_t)b * (Dn + En);
    for (int d = threadIdx.x; d < Dn; d += blockDim.x) dst[d] = src[d];
}

// ---------------- generic small-M GEMM: C[64,N] = A[64,K] @ W[N,K]^T (+bias[+bias2]) ----------------
__global__ void gemm_nt(const float* __restrict__ Amat,
                        const float* __restrict__ Wmat,
                        const float* __restrict__ bias,
                        const float* __restrict__ bias2,
                        float* __restrict__ Cmat,
                        int K, int N, int accumulate) {
    __shared__ float As[16][64];
    __shared__ float Ws[16][64];

    int tid = threadIdx.x;
    int tr = tid >> 4;
    int tc = tid & 15;
    int n0 = blockIdx.x * 64;

    int lm = tid >> 2;
    int lk = (tid & 3) * 4;

    float acc[4][4];
#pragma unroll
    for (int i = 0; i < 4; i++)
#pragma unroll
        for (int j = 0; j < 4; j++) acc[i][j] = 0.f;

    for (int k0 = 0; k0 < K; k0 += 16) {
        float4 a = *(const float4*)&Amat[(size_t)lm * K + k0 + lk];
        float4 w = *(const float4*)&Wmat[(size_t)(n0 + lm) * K + k0 + lk];
        As[lk + 0][lm] = a.x; As[lk + 1][lm] = a.y; As[lk + 2][lm] = a.z; As[lk + 3][lm] = a.w;
        Ws[lk + 0][lm] = w.x; Ws[lk + 1][lm] = w.y; Ws[lk + 2][lm] = w.z; Ws[lk + 3][lm] = w.w;
        __syncthreads();
#pragma unroll
        for (int k = 0; k < 16; k++) {
            float4 av = *(const float4*)&As[k][tr * 4];
            float4 wv = *(const float4*)&Ws[k][tc * 4];
            float ar[4] = {av.x, av.y, av.z, av.w};
            float wr[4] = {wv.x, wv.y, wv.z, wv.w};
#pragma unroll
            for (int i = 0; i < 4; i++)
#pragma unroll
                for (int j = 0; j < 4; j++) acc[i][j] += ar[i] * wr[j];
        }
        __syncthreads();
    }

#pragma unroll
    for (int i = 0; i < 4; i++) {
        int m = tr * 4 + i;
#pragma unroll
        for (int j = 0; j < 4; j++) {
            int n = n0 + tc * 4 + j;
            float v = acc[i][j];
            if (bias)  v += bias[n];
            if (bias2) v += bias2[n];
            if (accumulate) v += Cmat[(size_t)m * N + n];
            Cmat[(size_t)m * N + n] = v;
        }
    }
}

// ---------------- score init: score[i] = bva ----------------
__global__ void score_init_kernel(const float* __restrict__ bva, float* __restrict__ score) {
    int i = blockIdx.x * blockDim.x + threadIdx.x;
    if (i < Bn * Sn) score[i] = bva[0];
}

// ---------------- fused attention score GEMM (tf32 tensor cores) ----------------
// score[m] += sum_n va[n] * tanh( enc[m,:]·Wa_e[n,:] + q[b,n] + ba_e[n] )
// BM=128, BN=64, BK=32. block = 128 threads (4 warps).
// grid: (A/64 = 16, BS/128 = 512)  -- nblk fastest so CTAs sharing an enc tile co-reside.
__global__ __launch_bounds__(128) void score_gemm_mma(
        const float* __restrict__ enc,
        const float* __restrict__ Wa_e,
        const float* __restrict__ ba_e,
        const float* __restrict__ q,
        const float* __restrict__ va,
        float* __restrict__ score) {
    __shared__ unsigned As[128][36];
    __shared__ unsigned Ws[64][36];
    __shared__ float qb[64];
    __shared__ float vas[64];

    int tid = threadIdx.x;
    int w = tid >> 5;
    int lane = tid & 31;
    int g = lane >> 2;     // 0..7
    int tig = lane & 3;    // 0..3
    int n0 = blockIdx.x * 64;
    int m0 = blockIdx.y * 128;
    int b = m0 >> 10;      // all 128 rows in same batch (S=1024, 8 tiles per batch)

    if (tid < 64) {
        qb[tid]  = q[b * An + n0 + tid] + ba_e[n0 + tid];
        vas[tid] = va[n0 + tid];
    }

    float acc[2][8][4];
#pragma unroll
    for (int mt = 0; mt < 2; mt++)
#pragma unroll
        for (int nf = 0; nf < 8; nf++)
#pragma unroll
            for (int r = 0; r < 4; r++) acc[mt][nf][r] = 0.f;

    int lr = tid >> 3;          // 0..15
    int lc = (tid & 7) * 4;     // 0,4,...,28

    for (int k0 = 0; k0 < En; k0 += 32) {
        // global -> smem (coalesced: each warp reads 4 full rows of 128B)
#pragma unroll
        for (int it = 0; it < 8; it++) {
            int row = lr + it * 16;
            float4 v = *(const float4*)&enc[(size_t)(m0 + row) * En + k0 + lc];
            As[row][lc + 0] = f2tf(v.x);
            As[row][lc + 1] = f2tf(v.y);
            As[row][lc + 2] = f2tf(v.z);
            As[row][lc + 3] = f2tf(v.w);
        }
#pragma unroll
        for (int it = 0; it < 4; it++) {
            int row = lr + it * 16;
            float4 v = *(const float4*)&Wa_e[(size_t)(n0 + row) * En + k0 + lc];
            Ws[row][lc + 0] = f2tf(v.x);
            Ws[row][lc + 1] = f2tf(v.y);
            Ws[row][lc + 2] = f2tf(v.z);
            Ws[row][lc + 3] = f2tf(v.w);
        }
        __syncthreads();

#pragma unroll
        for (int ks = 0; ks < 4; ks++) {
            int kk = ks * 8 + tig;
            unsigned a0[4], a1[4];
            int r0 = w * 32 + g;
            a0[0] = As[r0][kk];       a0[1] = As[r0 + 8][kk];
            a0[2] = As[r0][kk + 4];   a0[3] = As[r0 + 8][kk + 4];
            a1[0] = As[r0 + 16][kk];     a1[1] = As[r0 + 24][kk];
            a1[2] = As[r0 + 16][kk + 4]; a1[3] = As[r0 + 24][kk + 4];
#pragma unroll
            for (int nf = 0; nf < 8; nf++) {
                unsigned bf[2];
                bf[0] = Ws[nf * 8 + g][kk];
                bf[1] = Ws[nf * 8 + g][kk + 4];
                mma_tf32(acc[0][nf], a0, bf);
                mma_tf32(acc[1][nf], a1, bf);
            }
        }
        __syncthreads();
    }

    // epilogue: tanh + va-weighted row reduction
#pragma unroll
    for (int mt = 0; mt < 2; mt++) {
        float sumlo = 0.f, sumhi = 0.f;
#pragma unroll
        for (int nf = 0; nf < 8; nf++) {
            int n = nf * 8 + 2 * tig;
            float q0 = qb[n], q1 = qb[n + 1];
            float v0 = vas[n], v1 = vas[n + 1];
            sumlo += v0 * tanhf(acc[mt][nf][0] + q0) + v1 * tanhf(acc[mt][nf][1] + q1);
            sumhi += v0 * tanhf(acc[mt][nf][2] + q0) + v1 * tanhf(acc[mt][nf][3] + q1);
        }
        sumlo += __shfl_xor_sync(0xffffffffu, sumlo, 1);
        sumlo += __shfl_xor_sync(0xffffffffu, sumlo, 2);
        sumhi += __shfl_xor_sync(0xffffffffu, sumhi, 1);
        sumhi += __shfl_xor_sync(0xffffffffu, sumhi, 2);
        if (tig == 0) {
            int rbase = m0 + w * 32 + mt * 16;
            atomicAdd(&score[rbase + g], sumlo);
            atomicAdd(&score[rbase + 8 + g], sumhi);
        }
    }
}

// ---------------- softmax over S per batch row ----------------
__global__ void softmax_kernel(const float* __restrict__ score, float* __restrict__ attn) {
    __shared__ float sh[Sn];
    __shared__ float red[256];
    int b = blockIdx.x;
    int tid = threadIdx.x;

    float lmax = -3.4e38f;
    for (int s = tid; s < Sn; s += 256) {
        float v = score[b * Sn + s];
        sh[s] = v;
        lmax = fmaxf(lmax, v);
    }
    red[tid] = lmax;
    __syncthreads();
    for (int off = 128; off > 0; off >>= 1) {
        if (tid < off) red[tid] = fmaxf(red[tid], red[tid + off]);
        __syncthreads();
    }
    float m = red[0];
    __syncthreads();

    float lsum = 0.f;
    for (int s = tid; s < Sn; s += 256) {
        float e = expf(sh[s] - m);
        sh[s] = e;
        lsum += e;
    }
    red[tid] = lsum;
    __syncthreads();
    for (int off = 128; off > 0; off >>= 1) {
        if (tid < off) red[tid] += red[tid + off];
        __syncthreads();
    }
    float inv = 1.f / red[0];
    __syncthreads();

    for (int s = tid; s < Sn; s += 256) attn[b * Sn + s] = sh[s] * inv;
}

// ---------------- context = attn @ enc (writes second half of x) ----------------
__global__ void context_kernel(const float* __restrict__ enc,
                               const float* __restrict__ attn,
                               float* __restrict__ xbuf) {
    __shared__ float w[Sn];
    int b = blockIdx.x;
    int e = blockIdx.y * 256 + threadIdx.x;
    for (int s = threadIdx.x; s < Sn; s += 256) w[s] = attn[b * Sn + s];
    __syncthreads();
    const float* ep = enc + (size_t)b * Sn * En + e;
    float acc = 0.f;
#pragma unroll 8
    for (int s = 0; s < Sn; s++) acc += w[s] * ep[(size_t)s * En];
    xbuf[(size_t)b * (Dn + En) + Dn + e] = acc;
}

// ---------------- LSTM pointwise ----------------
__global__ void lstm_pointwise(const float* __restrict__ gates,
                               const float* __restrict__ cprev,
                               float* __restrict__ hout,
                               float* __restrict__ cout) {
    int idx = blockIdx.x * 256 + threadIdx.x;
    if (idx >= Bn * Hn) return;
    int b = idx >> 10;
    int h = idx & 1023;
    const float* g = gates + (size_t)b * 4 * Hn;
    float ig = 1.f / (1.f + expf(-g[h]));
    float fg = 1.f / (1.f + expf(-g[Hn + h]));
    float gg = tanhf(g[2 * Hn + h]);
    float og = 1.f / (1.f + expf(-g[3 * Hn + h]));
    float c = fg * cprev[idx] + ig * gg;
    hout[idx] = og * tanhf(c);
    cout[idx] = c;
}

// ---------------- launcher ----------------
extern "C" void kernel_launch(void* const* d_in, const int* in_sizes, int n_in,
                              void* d_out, int out_size) {
    const int*   input_step = (const int*)d_in[0];
    const float* h0    = (const float*)d_in[1];
    const float* c0    = (const float*)d_in[2];
    const float* enc   = (const float*)d_in[3];
    const float* emb   = (const float*)d_in[4];
    const float* Wa_h  = (const float*)d_in[5];
    const float* ba_h  = (const float*)d_in[6];
    const float* Wa_e  = (const float*)d_in[7];
    const float* ba_e  = (const float*)d_in[8];
    const float* va    = (const float*)d_in[9];
    const float* bva   = (const float*)d_in[10];
    const float* Wih0  = (const float*)d_in[11];
    const float* Whh0  = (const float*)d_in[12];
    const float* bih0  = (const float*)d_in[13];
    const float* bhh0  = (const float*)d_in[14];
    const float* Wih1  = (const float*)d_in[15];
    const float* Whh1  = (const float*)d_in[16];
    const float* bih1  = (const float*)d_in[17];
    const float* bhh1  = (const float*)d_in[18];
    const float* Wout  = (const float*)d_in[19];
    const float* bout  = (const float*)d_in[20];

    float* out = (float*)d_out;
    float* out_logits = out;                      // B*V
    float* out_h      = out_logits + Bn * Vn;     // 2*B*H
    float* out_c      = out_h + 2 * Bn * Hn;      // 2*B*H
    float* out_attn   = out_c + 2 * Bn * Hn;      // B*S

    float* q_buf;     cudaGetSymbolAddress((void**)&q_buf, g_q);
    float* score_buf; cudaGetSymbolAddress((void**)&score_buf, g_score);
    float* x_buf;     cudaGetSymbolAddress((void**)&x_buf, g_x);
    float* gates_buf; cudaGetSymbolAddress((void**)&gates_buf, g_gates);

    // 1. embedding gather -> x[:, :D]
    embed_kernel<<<Bn, 256>>>(input_step, emb, x_buf);

    // 2. q = h0[1] @ Wa_h^T + ba_h
    gemm_nt<<<An / 64, 256>>>(h0 + Bn * Hn, Wa_h, ba_h, nullptr, q_buf, Hn, An, 0);

    // 3. score init to bva, then fused tf32 tensor-core score GEMM
    score_init_kernel<<<(Bn * Sn + 255) / 256, 256>>>(bva, score_buf);
    {
        dim3 grid(An / 64, Bn * Sn / 128);  // x = n-block fastest -> enc tile reuse in L2
        score_gemm_mma<<<grid, 128>>>(enc, Wa_e, ba_e, q_buf, va, score_buf);
    }

    // 4. softmax -> attn_w output
    softmax_kernel<<<Bn, 256>>>(score_buf, out_attn);

    // 5. context -> x[:, D:]
    {
        dim3 grid(Bn, En / 256);
        context_kernel<<<grid, 256>>>(enc, out_attn, x_buf);
    }

    // 6. LSTM layer 0
    gemm_nt<<<4 * Hn / 64, 256>>>(x_buf, Wih0, bih0, bhh0, gates_buf, Dn + En, 4 * Hn, 0);
    gemm_nt<<<4 * Hn / 64, 256>>>(h0, Whh0, nullptr, nullptr, gates_buf, Hn, 4 * Hn, 1);
    lstm_pointwise<<<(Bn * Hn + 255) / 256, 256>>>(gates_buf, c0, out_h, out_c);

    // 7. LSTM layer 1
    gemm_nt<<<4 * Hn / 64, 256>>>(out_h, Wih1, bih1, bhh1, gates_buf, Hn, 4 * Hn, 0);
    gemm_nt<<<4 * Hn / 64, 256>>>(h0 + Bn * Hn, Whh1, nullptr, nullptr, gates_buf, Hn, 4 * Hn, 1);
    lstm_pointwise<<<(Bn * Hn + 255) / 256, 256>>>(gates_buf, c0 + Bn * Hn,
                                                   out_h + Bn * Hn, out_c + Bn * Hn);

    // 8. logits = h2 @ Wout^T + bout
    gemm_nt<<<Vn / 64, 256>>>(out_h + Bn * Hn, Wout, bout, nullptr, out_logits, Hn, Vn, 0);
}